// round 5
// baseline (speedup 1.0000x reference)
#include <cuda_runtime.h>
#include <math.h>

// ParallelRNN: B=4096, H=256, L=32, I=64 (fp32 everywhere)
// R2: 128-thread CTAs, BT=32, ~100KB smem -> 2 CTAs/SM so independent CTAs
// cover each other's barrier/cp.async stalls. Micro-tile stays 4x16 (f32x2).

#define DEVI __device__ __forceinline__

static constexpr int Bb   = 4096;
static constexpr int Hh   = 256;
static constexpr int Ll   = 32;
static constexpr int Ii   = 64;
static constexpr int BT   = 32;          // batch rows per block
static constexpr int NT   = 128;         // threads per block
static constexpr int HS   = 258;         // bufA/bufB row stride (floats)
static constexpr int XS   = 68;          // xm row stride
static constexpr int WK   = 8;           // weight tile K rows
static constexpr int WS   = 256;         // weight tile row stride (floats, no pad needed)
static constexpr int BHL  = Bb * Hh * Ll;    // 33554432
static constexpr int BL   = Bb * Ll;         // 131072

// smem layout (floats)
static constexpr int OFF_A   = 0;
static constexpr int OFF_B   = OFF_A + BT * HS;          // 8256
static constexpr int OFF_W   = OFF_B + BT * HS;          // 16512
static constexpr int OFF_XM  = OFF_W + 3 * WK * WS;      // 22656
static constexpr int OFF_WMU = OFF_XM + BT * XS;         // 24832
static constexpr int SMEM_FLOATS = OFF_WMU + 256;        // 25088
static constexpr int SMEM_BYTES  = SMEM_FLOATS * 4;      // 100352  -> 2 CTAs/SM

DEVI unsigned int s2u(const void* p) {
    unsigned int a;
    asm("{ .reg .u64 t; cvta.to.shared.u64 t, %1; cvt.u32.u64 %0, t; }"
        : "=r"(a) : "l"(p));
    return a;
}

DEVI void ffma2(unsigned long long& d, unsigned long long a, unsigned long long b) {
    asm("fma.rn.f32x2 %0, %1, %2, %0;" : "+l"(d) : "l"(a), "l"(b));
}

DEVI unsigned long long packf2(float x, float y) {
    unsigned long long v;
    asm("mov.b64 %0, {%1, %2};" : "=l"(v) : "f"(x), "f"(y));
    return v;
}

DEVI float2 unpackf2(unsigned long long v) {
    float2 f;
    asm("mov.b64 {%0, %1}, %2;" : "=f"(f.x), "=f"(f.y) : "l"(v));
    return f;
}

DEVI float sigm(float v) { return __fdividef(1.0f, 1.0f + __expf(-v)); }

// copy one WK x 256 weight tile (kt-th) into wbuf slot `buf` via cp.async
DEVI void issue_tile(const float* __restrict__ gW, int kt, int buf,
                     unsigned int wsm_u32, int tid) {
    const float* gsrc = gW + kt * WK * Hh;
    unsigned int sbase = wsm_u32 + (unsigned int)buf * (WK * WS * 4);
#pragma unroll
    for (int q = 0; q < 4; ++q) {                 // WK*64 f4 / 128 thr = 4
        int idx = tid + NT * q;
        int row = idx >> 6;
        int c4  = idx & 63;
        unsigned int sa = sbase + (unsigned int)(row * WS + c4 * 4) * 4u;
        const float* ga = gsrc + row * Hh + c4 * 4;
        asm volatile("cp.async.cg.shared.global [%0], [%1], 16;"
                     :: "r"(sa), "l"(ga));
    }
}

// acc[r][p] += in_s[BT x KTOT] @ gW[KTOT x 256] for this thread's micro-tile
template <int KTOT, int INSTRIDE>
DEVI void gemm_pass(unsigned long long acc[4][8], const float* __restrict__ gW,
                    const float* in_s, const float* wsm, unsigned int wsm_u32,
                    int tid, int tr4, int tc) {
    constexpr int T = KTOT / WK;
    issue_tile(gW, 0, 0, wsm_u32, tid);
    asm volatile("cp.async.commit_group;");
    for (int t = 0; t < T; ++t) {
        if (t + 1 < T) issue_tile(gW, t + 1, (t + 1) % 3, wsm_u32, tid);
        asm volatile("cp.async.commit_group;");
        asm volatile("cp.async.wait_group 1;");
        __syncthreads();
        const float* wb   = wsm + (t % 3) * (WK * WS);
        const float* arow = in_s + tr4 * INSTRIDE + t * WK;
#pragma unroll
        for (int k = 0; k < WK; ++k) {
            unsigned long long hp[4];
#pragma unroll
            for (int r = 0; r < 4; ++r) {
                float hv = arow[r * INSTRIDE + k];
                hp[r] = packf2(hv, hv);
            }
            const float* wr = wb + k * WS + tc * 4;
#pragma unroll
            for (int j = 0; j < 4; ++j) {
                float4 w4 = *reinterpret_cast<const float4*>(wr + 64 * j);
                unsigned long long w01 = packf2(w4.x, w4.y);
                unsigned long long w23 = packf2(w4.z, w4.w);
#pragma unroll
                for (int r = 0; r < 4; ++r) {
                    ffma2(acc[r][2 * j],     hp[r], w01);
                    ffma2(acc[r][2 * j + 1], hp[r], w23);
                }
            }
        }
    }
    __syncthreads();   // protect wbuf slot 0 before the next pass's prologue
}

__global__ void __launch_bounds__(NT, 2)
prnn_kernel(const float* __restrict__ hidden, const float* __restrict__ x,
            const float* __restrict__ mask,
            const float* __restrict__ Wir, const float* __restrict__ bir,
            const float* __restrict__ Wiz, const float* __restrict__ biz,
            const float* __restrict__ Win, const float* __restrict__ bin_,
            const float* __restrict__ Whr, const float* __restrict__ Whz,
            const float* __restrict__ Whn, const float* __restrict__ bhn,
            const float* __restrict__ W1,  const float* __restrict__ b1,
            const float* __restrict__ W2,  const float* __restrict__ b2,
            const float* __restrict__ Wmu, const float* __restrict__ bmu,
            const float* __restrict__ log_var, float* __restrict__ out) {
    extern __shared__ float smem[];
    float* bufA  = smem + OFF_A;
    float* bufB  = smem + OFF_B;
    float* wsm   = smem + OFF_W;
    float* xm    = smem + OFF_XM;
    float* wmu_s = smem + OFF_WMU;
    const unsigned int wsm_u32 = s2u(wsm);

    const int tid = threadIdx.x;
    const int tc  = tid & 15;
    const int tr4 = (tid >> 4) * 4;          // 8 row groups -> rows 0..31
    const int bx  = blockIdx.x;
    const int l   = bx & 31;
    const int b0  = (bx >> 5) * BT;

    // ---- load h tile: bufA[row][col] = hidden[b0+row, col, l] ----
#pragma unroll 4
    for (int q = 0; q < BT; ++q) {
        const float* hb = hidden + (size_t)(b0 + q) * (Hh * Ll) + l;
        bufA[q * HS + tid]      = hb[tid * Ll];
        bufA[q * HS + tid + NT] = hb[(tid + NT) * Ll];
    }
    // ---- masked input tile: xm[row][i] = x[b0+row, i] * mask[i, l] ----
#pragma unroll
    for (int q = 0; q < 16; ++q) {
        int idx = tid + NT * q;
        int row = idx >> 6, i = idx & 63;
        xm[row * XS + i] = x[(b0 + row) * Ii + i] * mask[i * Ll + l];
    }
    wmu_s[tid]      = Wmu[l * Hh + tid];
    wmu_s[tid + NT] = Wmu[l * Hh + tid + NT];
    // (no explicit sync needed: first gemm_pass syncs before any compute)

    unsigned long long acc[4][8];
    unsigned long long rn[4][8];

    // ================= pass A: r = sigmoid(hh_r + xi_r + bir) =================
#pragma unroll
    for (int r = 0; r < 4; ++r)
#pragma unroll
        for (int p = 0; p < 8; ++p) acc[r][p] = 0ull;
    gemm_pass<256, HS>(acc, Whr + l * Hh * Hh, bufA, wsm, wsm_u32, tid, tr4, tc);
    gemm_pass<64,  XS>(acc, Wir + l * Ii * Hh, xm,   wsm, wsm_u32, tid, tr4, tc);
    {
        const float* bb = bir + l * Hh;
#pragma unroll
        for (int r = 0; r < 4; ++r)
#pragma unroll
            for (int p = 0; p < 8; ++p) {
                int cp = tc * 4 + (p >> 1) * 64 + (p & 1) * 2;
                float2 a = unpackf2(acc[r][p]);
                rn[r][p] = packf2(sigm(a.x + bb[cp]), sigm(a.y + bb[cp + 1]));
            }
    }

    // ============ pass B: n = tanh(xi_n + bin + r*(hh_n + bhn)) ============
#pragma unroll
    for (int r = 0; r < 4; ++r)
#pragma unroll
        for (int p = 0; p < 8; ++p) acc[r][p] = 0ull;
    gemm_pass<256, HS>(acc, Whn + l * Hh * Hh, bufA, wsm, wsm_u32, tid, tr4, tc);
    {
        const float* bb = bhn + l * Hh;
#pragma unroll
        for (int r = 0; r < 4; ++r)
#pragma unroll
            for (int p = 0; p < 8; ++p) {
                int cp = tc * 4 + (p >> 1) * 64 + (p & 1) * 2;
                float2 a  = unpackf2(acc[r][p]);
                float2 rr = unpackf2(rn[r][p]);
                acc[r][p] = packf2(rr.x * (a.x + bb[cp]),
                                   rr.y * (a.y + bb[cp + 1]));
            }
    }
    gemm_pass<64, XS>(acc, Win + l * Ii * Hh, xm, wsm, wsm_u32, tid, tr4, tc);
    {
        const float* bb = bin_ + l * Hh;
#pragma unroll
        for (int r = 0; r < 4; ++r)
#pragma unroll
            for (int p = 0; p < 8; ++p) {
                int cp = tc * 4 + (p >> 1) * 64 + (p & 1) * 2;
                float2 a = unpackf2(acc[r][p]);
                rn[r][p] = packf2(tanhf(a.x + bb[cp]), tanhf(a.y + bb[cp + 1]));
            }
    }

    // ====== pass C: z = sigmoid(hh_z + xi_z + biz); hnew = n + z*(h-n) ======
#pragma unroll
    for (int r = 0; r < 4; ++r)
#pragma unroll
        for (int p = 0; p < 8; ++p) acc[r][p] = 0ull;
    gemm_pass<256, HS>(acc, Whz + l * Hh * Hh, bufA, wsm, wsm_u32, tid, tr4, tc);
    gemm_pass<64,  XS>(acc, Wiz + l * Ii * Hh, xm,   wsm, wsm_u32, tid, tr4, tc);
    {
        const float* bb = biz + l * Hh;
#pragma unroll
        for (int r = 0; r < 4; ++r)
#pragma unroll
            for (int p = 0; p < 8; ++p) {
                int cp = tc * 4 + (p >> 1) * 64 + (p & 1) * 2;
                float2 a  = unpackf2(acc[r][p]);
                float2 nn = unpackf2(rn[r][p]);
                float zx = sigm(a.x + bb[cp]);
                float zy = sigm(a.y + bb[cp + 1]);
                float hx = bufA[(tr4 + r) * HS + cp];
                float hy = bufA[(tr4 + r) * HS + cp + 1];
                float2 hv;
                hv.x = nn.x + zx * (hx - nn.x);
                hv.y = nn.y + zy * (hy - nn.y);
                *reinterpret_cast<float2*>(&bufB[(tr4 + r) * HS + cp]) = hv;
            }
    }

    // ================= pass D: h1 = relu(hnew @ W1 + b1) =================
#pragma unroll
    for (int r = 0; r < 4; ++r)
#pragma unroll
        for (int p = 0; p < 8; ++p) acc[r][p] = 0ull;
    gemm_pass<256, HS>(acc, W1 + l * Hh * Hh, bufB, wsm, wsm_u32, tid, tr4, tc);
    {
        const float* bb = b1 + l * Hh;
#pragma unroll
        for (int r = 0; r < 4; ++r)
#pragma unroll
            for (int p = 0; p < 8; ++p) {
                int cp = tc * 4 + (p >> 1) * 64 + (p & 1) * 2;
                float2 a = unpackf2(acc[r][p]);
                float2 hv;
                hv.x = fmaxf(a.x + bb[cp], 0.0f);
                hv.y = fmaxf(a.y + bb[cp + 1], 0.0f);
                *reinterpret_cast<float2*>(&bufA[(tr4 + r) * HS + cp]) = hv;
            }
    }

    // ======== pass E: h2 = relu(h1 @ W2 + b2); store + mu reduction ========
#pragma unroll
    for (int r = 0; r < 4; ++r)
#pragma unroll
        for (int p = 0; p < 8; ++p) acc[r][p] = 0ull;
    gemm_pass<256, HS>(acc, W2 + l * Hh * Hh, bufA, wsm, wsm_u32, tid, tr4, tc);
    float mup[4] = {0.f, 0.f, 0.f, 0.f};
    {
        const float* bb = b2 + l * Hh;
#pragma unroll
        for (int r = 0; r < 4; ++r) {
            int brow = b0 + tr4 + r;
#pragma unroll
            for (int p = 0; p < 8; ++p) {
                int cp = tc * 4 + (p >> 1) * 64 + (p & 1) * 2;
                float2 a = unpackf2(acc[r][p]);
                float h2x = fmaxf(a.x + bb[cp], 0.0f);
                float h2y = fmaxf(a.y + bb[cp + 1], 0.0f);
                // transposed store: out[b, hcol, l]
                out[(size_t)brow * (Hh * Ll) + cp * Ll + l]       = h2x;
                out[(size_t)brow * (Hh * Ll) + (cp + 1) * Ll + l] = h2y;
                mup[r] += h2x * wmu_s[cp] + h2y * wmu_s[cp + 1];
            }
        }
    }
    // reduce mu over the 16 column-threads (lanes 0..15 / 16..31 per warp)
#pragma unroll
    for (int r = 0; r < 4; ++r) {
#pragma unroll
        for (int o = 8; o >= 1; o >>= 1)
            mup[r] += __shfl_down_sync(0xffffffffu, mup[r], o, 16);
    }
    if (tc == 0) {
        float lvv = fmaxf(log_var[l], -3.0f);
        float bm  = bmu[l];
#pragma unroll
        for (int r = 0; r < 4; ++r) {
            int brow = b0 + tr4 + r;
            out[BHL + brow * Ll + l]      = mup[r] + bm;
            out[BHL + BL + brow * Ll + l] = lvv;
        }
    }
}

extern "C" void kernel_launch(void* const* d_in, const int* in_sizes, int n_in,
                              void* d_out, int out_size) {
    const float* hidden  = (const float*)d_in[0];
    const float* x       = (const float*)d_in[1];
    const float* mask    = (const float*)d_in[2];
    const float* Wir     = (const float*)d_in[3];
    const float* bir     = (const float*)d_in[4];
    const float* Wiz     = (const float*)d_in[5];
    const float* biz     = (const float*)d_in[6];
    const float* Win     = (const float*)d_in[7];
    const float* bin_    = (const float*)d_in[8];
    const float* Whr     = (const float*)d_in[9];
    const float* Whz     = (const float*)d_in[10];
    const float* Whn     = (const float*)d_in[11];
    const float* bhn     = (const float*)d_in[12];
    const float* W1      = (const float*)d_in[13];
    const float* b1      = (const float*)d_in[14];
    const float* W2      = (const float*)d_in[15];
    const float* b2      = (const float*)d_in[16];
    const float* Wmu     = (const float*)d_in[17];
    const float* bmu     = (const float*)d_in[18];
    const float* log_var = (const float*)d_in[19];
    float* out = (float*)d_out;

    cudaFuncSetAttribute(prnn_kernel,
                         cudaFuncAttributeMaxDynamicSharedMemorySize, SMEM_BYTES);

    dim3 grid(Ll * (Bb / BT));   // 4096 blocks, l fastest -> L2 weight reuse
    dim3 block(NT);
    prnn_kernel<<<grid, block, SMEM_BYTES>>>(
        hidden, x, mask, Wir, bir, Wiz, biz, Win, bin_,
        Whr, Whz, Whn, bhn, W1, b1, W2, b2, Wmu, bmu, log_var, out);
}

// round 7
// speedup vs baseline: 1.7454x; 1.7454x over previous
#include <cuda_runtime.h>
#include <math.h>
#include <stdint.h>

// ParallelRNN via warp-level tf32 mma.sync (base sm_103 PTX; tcgen05 is
// unavailable on this toolchain target). B=4096,H=256,L=32,I=64.
// CTA = (l, 128 rows) x 256 thr; warp tile 64x64; A in smem (in-place chain),
// weights streamed natural-layout via 3-buffer cp.async; r/n in gmem scratch.

#define DEVI __device__ __forceinline__

static constexpr long long BHL = 4096LL * 256 * 32;
static constexpr long long BLc = 4096LL * 32;

__device__ float g_scr[33554432];   // 128MB per-thread scratch (r, then n)

// smem map (bytes): A[0,131072) xm[131072,163840) B 3x8448[163840,189184)
//                   mu[189184,189696) wmu[189696,190720)
static constexpr unsigned SMEM_BYTES = 190720;

DEVI unsigned s2u(const void* p) {
    unsigned a;
    asm("{ .reg .u64 t; cvta.to.shared.u64 t, %1; cvt.u32.u64 %0, t; }"
        : "=r"(a) : "l"(p));
    return a;
}
DEVI float sigm(float v) { return __fdividef(1.f, 1.f + __expf(-v)); }
// 16B-unit swizzle: phys unit p = (k4 & ~7) | ((k4 ^ row) & 7)
DEVI unsigned aswz(int row, int k4) {
    return (unsigned)(((k4 & ~7) | ((k4 ^ row) & 7)) * 16);
}

// ---- one GEMM segment: acc += Asm[128 x 8*nch] @ W[8*nch x 256] ----
template <int RS>   // A row stride in bytes (1024 for A, 256 for xm)
DEVI void gemm_seg(float (&acc)[4][8][4], unsigned aU, const float* __restrict__ W,
                   int nch, unsigned bU, int tid, int lane, int wr, int wc) {
#pragma unroll
    for (int q = 0; q < 2; ++q) {                       // chunk 0 -> buf 0
        int f = tid + q * 256, k = f >> 6, u = f & 63;
        asm volatile("cp.async.cg.shared.global [%0], [%1], 16;"
                     :: "r"(bU + k * 1056 + u * 16),
                        "l"((const char*)W + (size_t)k * 1024 + u * 16));
    }
    asm volatile("cp.async.commit_group;");
    const int lm = lane >> 3, lr = lane & 7;
    for (int c = 0; c < nch; ++c) {
        if (c + 1 < nch) {
            const char* src = (const char*)W + (size_t)(c + 1) * 8192;
            unsigned dst = bU + ((c + 1) % 3) * 8448u;
#pragma unroll
            for (int q = 0; q < 2; ++q) {
                int f = tid + q * 256, k = f >> 6, u = f & 63;
                asm volatile("cp.async.cg.shared.global [%0], [%1], 16;"
                             :: "r"(dst + k * 1056 + u * 16),
                                "l"(src + (size_t)k * 1024 + u * 16));
            }
        }
        asm volatile("cp.async.commit_group;");
        asm volatile("cp.async.wait_group 1;");
        __syncthreads();
        const unsigned bb = bU + (c % 3) * 8448u;
        uint32_t af[4][4];
#pragma unroll
        for (int i = 0; i < 4; ++i) {
            int row = wr * 64 + i * 16 + (lm & 1) * 8 + lr;
            int k4  = c * 2 + (lm >> 1);
            unsigned ad = aU + (unsigned)row * RS + aswz(row, k4);
            asm volatile("ldmatrix.sync.aligned.m8n8.x4.shared.b16 {%0,%1,%2,%3}, [%4];"
                : "=r"(af[i][0]), "=r"(af[i][1]), "=r"(af[i][2]), "=r"(af[i][3])
                : "r"(ad));
#pragma unroll
            for (int q = 0; q < 4; ++q)
                asm volatile("{.reg .f32 t; mov.b32 t, %0; cvt.rna.tf32.f32 %0, t;}"
                             : "+r"(af[i][q]));
        }
        uint32_t bf[8][2];
#pragma unroll
        for (int j = 0; j < 8; ++j) {
            unsigned b0a = bb + (unsigned)(lane & 3) * 1056u
                         + (unsigned)(wc * 64 + j * 8 + (lane >> 2)) * 4u;
            float v0, v1;
            asm volatile("ld.shared.f32 %0, [%1];" : "=f"(v0) : "r"(b0a));
            asm volatile("ld.shared.f32 %0, [%1];" : "=f"(v1) : "r"(b0a + 4224u));
            asm volatile("cvt.rna.tf32.f32 %0, %1;" : "=r"(bf[j][0]) : "f"(v0));
            asm volatile("cvt.rna.tf32.f32 %0, %1;" : "=r"(bf[j][1]) : "f"(v1));
        }
#pragma unroll
        for (int i = 0; i < 4; ++i)
#pragma unroll
            for (int j = 0; j < 8; ++j)
                asm volatile(
                    "mma.sync.aligned.m16n8k8.row.col.f32.tf32.tf32.f32 "
                    "{%0,%1,%2,%3}, {%4,%5,%6,%7}, {%8,%9}, {%0,%1,%2,%3};"
                    : "+f"(acc[i][j][0]), "+f"(acc[i][j][1]),
                      "+f"(acc[i][j][2]), "+f"(acc[i][j][3])
                    : "r"(af[i][0]), "r"(af[i][1]), "r"(af[i][2]), "r"(af[i][3]),
                      "r"(bf[j][0]), "r"(bf[j][1]));
    }
    __syncthreads();   // all reads of A/B done before any epilogue write / reuse
}

__global__ void __launch_bounds__(256, 1)
prnn_mma(const float* __restrict__ hidden, const float* __restrict__ x,
         const float* __restrict__ mask,
         const float* __restrict__ Wir, const float* __restrict__ bir,
         const float* __restrict__ Wiz, const float* __restrict__ biz,
         const float* __restrict__ Win, const float* __restrict__ bin_,
         const float* __restrict__ Whr, const float* __restrict__ Whz,
         const float* __restrict__ Whn, const float* __restrict__ bhn,
         const float* __restrict__ W1,  const float* __restrict__ b1,
         const float* __restrict__ W2,  const float* __restrict__ b2,
         const float* __restrict__ Wmu, const float* __restrict__ bmu,
         const float* __restrict__ log_var, float* __restrict__ out) {
    extern __shared__ __align__(16) char smem[];
    const unsigned sU = s2u(smem);
    const unsigned aU = sU, xU = sU + 131072u, bU = sU + 163840u;
    float* mu_s  = (float*)(smem + 189184);
    float* wmu_s = (float*)(smem + 189696);
    const int tid = threadIdx.x, lane = tid & 31, w = tid >> 5;
    const int wr = w >> 2, wc = w & 3;
    const int l = blockIdx.x & 31, b0 = (blockIdx.x >> 5) * 128;

    if (tid < 128) mu_s[tid] = 0.f;
    wmu_s[tid] = __ldg(Wmu + l * 256 + tid);

    {   // A <- h (scattered gmem, swizzled smem)
        const float* hp = hidden + (size_t)b0 * 8192 + (size_t)tid * 32 + l;
#pragma unroll 4
        for (int r = 0; r < 128; ++r) {
            float v = hp[(size_t)r * 8192];
            unsigned ad = aU + (unsigned)r * 1024u + aswz(r, tid >> 2) + (tid & 3) * 4u;
            asm volatile("st.shared.f32 [%0], %1;" :: "r"(ad), "f"(v));
        }
    }
    {   // xm <- x * mask
#pragma unroll
        for (int q = 0; q < 32; ++q) {
            int idx = tid + q * 256, r = idx >> 6, k = idx & 63;
            float v = __ldg(x + (size_t)(b0 + r) * 64 + k) * __ldg(mask + k * 32 + l);
            unsigned ad = xU + (unsigned)r * 256u + aswz(r, k >> 2) + (k & 3) * 4u;
            asm volatile("st.shared.f32 [%0], %1;" :: "r"(ad), "f"(v));
        }
    }

    float acc[4][8][4];
    float* scr = g_scr + (size_t)blockIdx.x * 32768 + (size_t)w * 4096;

#define ZACC()                                                                \
    _Pragma("unroll") for (int i = 0; i < 4; ++i)                             \
    _Pragma("unroll") for (int j = 0; j < 8; ++j)                             \
    _Pragma("unroll") for (int q = 0; q < 4; ++q) acc[i][j][q] = 0.f;
#define C0J (wc * 64 + j * 8 + 2 * (lane & 3))
#define R0I (wr * 64 + i * 16 + (lane >> 2))
#define SCRP(i, j) (scr + ((size_t)((i) * 8 + (j)) * 32 + lane) * 4)

    // seg1: r = sigmoid(h@Whr + xm@Wir + bir) -> scratch
    ZACC();
    gemm_seg<1024>(acc, aU, Whr + (size_t)l * 65536, 32, bU, tid, lane, wr, wc);
    gemm_seg<256>(acc, xU, Wir + (size_t)l * 16384, 8, bU, tid, lane, wr, wc);
    {
        const float* bb = bir + l * 256;
#pragma unroll
        for (int i = 0; i < 4; ++i)
#pragma unroll
            for (int j = 0; j < 8; ++j) {
                int c0 = C0J;
                float4 v;
                v.x = sigm(acc[i][j][0] + __ldg(bb + c0));
                v.y = sigm(acc[i][j][1] + __ldg(bb + c0 + 1));
                v.z = sigm(acc[i][j][2] + __ldg(bb + c0));
                v.w = sigm(acc[i][j][3] + __ldg(bb + c0 + 1));
                *reinterpret_cast<float4*>(SCRP(i, j)) = v;
            }
    }
    // seg2: acc = h@Whn; t = r*(acc+bhn); acc = t; acc += xm@Win; n = tanh(acc+bin)
    ZACC();
    gemm_seg<1024>(acc, aU, Whn + (size_t)l * 65536, 32, bU, tid, lane, wr, wc);
    {
        const float* bb = bhn + l * 256;
#pragma unroll
        for (int i = 0; i < 4; ++i)
#pragma unroll
            for (int j = 0; j < 8; ++j) {
                int c0 = C0J;
                float4 rv = *reinterpret_cast<const float4*>(SCRP(i, j));
                acc[i][j][0] = rv.x * (acc[i][j][0] + __ldg(bb + c0));
                acc[i][j][1] = rv.y * (acc[i][j][1] + __ldg(bb + c0 + 1));
                acc[i][j][2] = rv.z * (acc[i][j][2] + __ldg(bb + c0));
                acc[i][j][3] = rv.w * (acc[i][j][3] + __ldg(bb + c0 + 1));
            }
    }
    gemm_seg<256>(acc, xU, Win + (size_t)l * 16384, 8, bU, tid, lane, wr, wc);
    {
        const float* bb = bin_ + l * 256;
#pragma unroll
        for (int i = 0; i < 4; ++i)
#pragma unroll
            for (int j = 0; j < 8; ++j) {
                int c0 = C0J;
                float4 v;
                v.x = tanhf(acc[i][j][0] + __ldg(bb + c0));
                v.y = tanhf(acc[i][j][1] + __ldg(bb + c0 + 1));
                v.z = tanhf(acc[i][j][2] + __ldg(bb + c0));
                v.w = tanhf(acc[i][j][3] + __ldg(bb + c0 + 1));
                *reinterpret_cast<float4*>(SCRP(i, j)) = v;
            }
    }
    // seg3: z = sigmoid(h@Whz + xm@Wiz + biz); hnew = n + z*(h-n) -> A (in place)
    ZACC();
    gemm_seg<1024>(acc, aU, Whz + (size_t)l * 65536, 32, bU, tid, lane, wr, wc);
    gemm_seg<256>(acc, xU, Wiz + (size_t)l * 16384, 8, bU, tid, lane, wr, wc);
    {
        const float* bb = biz + l * 256;
#pragma unroll
        for (int i = 0; i < 4; ++i)
#pragma unroll
            for (int j = 0; j < 8; ++j) {
                int c0 = C0J, r0 = R0I, r1 = r0 + 8;
                float4 nv = *reinterpret_cast<const float4*>(SCRP(i, j));
                float zz[4];
                zz[0] = sigm(acc[i][j][0] + __ldg(bb + c0));
                zz[1] = sigm(acc[i][j][1] + __ldg(bb + c0 + 1));
                zz[2] = sigm(acc[i][j][2] + __ldg(bb + c0));
                zz[3] = sigm(acc[i][j][3] + __ldg(bb + c0 + 1));
                const int rr[4] = {r0, r0, r1, r1};
                const int cc[4] = {c0, c0 + 1, c0, c0 + 1};
                const float nn[4] = {nv.x, nv.y, nv.z, nv.w};
#pragma unroll
                for (int q = 0; q < 4; ++q) {
                    unsigned ad = aU + (unsigned)rr[q] * 1024u
                                + aswz(rr[q], cc[q] >> 2) + (cc[q] & 3) * 4u;
                    float h;
                    asm volatile("ld.shared.f32 %0, [%1];" : "=f"(h) : "r"(ad));
                    float hv = nn[q] + zz[q] * (h - nn[q]);
                    asm volatile("st.shared.f32 [%0], %1;" :: "r"(ad), "f"(hv));
                }
            }
    }
    __syncthreads();
    // seg4: h1 = relu(hnew@W1 + b1) -> A
    ZACC();
    gemm_seg<1024>(acc, aU, W1 + (size_t)l * 65536, 32, bU, tid, lane, wr, wc);
    {
        const float* bb = b1 + l * 256;
#pragma unroll
        for (int i = 0; i < 4; ++i)
#pragma unroll
            for (int j = 0; j < 8; ++j) {
                int c0 = C0J, r0 = R0I, r1 = r0 + 8;
                const int rr[4] = {r0, r0, r1, r1};
                const int cc[4] = {c0, c0 + 1, c0, c0 + 1};
#pragma unroll
                for (int q = 0; q < 4; ++q) {
                    float hv = fmaxf(acc[i][j][q] + __ldg(bb + cc[q]), 0.f);
                    unsigned ad = aU + (unsigned)rr[q] * 1024u
                                + aswz(rr[q], cc[q] >> 2) + (cc[q] & 3) * 4u;
                    asm volatile("st.shared.f32 [%0], %1;" :: "r"(ad), "f"(hv));
                }
            }
    }
    __syncthreads();
    // seg5: h2 = relu(h1@W2 + b2) -> out (scattered) + mu
    ZACC();
    gemm_seg<1024>(acc, aU, W2 + (size_t)l * 65536, 32, bU, tid, lane, wr, wc);
    {
        const float* bb = b2 + l * 256;
        float mup[4][2];
#pragma unroll
        for (int i = 0; i < 4; ++i) { mup[i][0] = 0.f; mup[i][1] = 0.f; }
#pragma unroll
        for (int i = 0; i < 4; ++i)
#pragma unroll
            for (int j = 0; j < 8; ++j) {
                int c0 = C0J, r0 = R0I, r1 = r0 + 8;
                float h2a = fmaxf(acc[i][j][0] + __ldg(bb + c0), 0.f);
                float h2b = fmaxf(acc[i][j][1] + __ldg(bb + c0 + 1), 0.f);
                float h2c = fmaxf(acc[i][j][2] + __ldg(bb + c0), 0.f);
                float h2d = fmaxf(acc[i][j][3] + __ldg(bb + c0 + 1), 0.f);
                size_t ob = (size_t)(b0 + r0) * 8192 + l;
                size_t ob1 = (size_t)(b0 + r1) * 8192 + l;
                out[ob + (size_t)c0 * 32]        = h2a;
                out[ob + (size_t)(c0 + 1) * 32]  = h2b;
                out[ob1 + (size_t)c0 * 32]       = h2c;
                out[ob1 + (size_t)(c0 + 1) * 32] = h2d;
                mup[i][0] += h2a * wmu_s[c0] + h2b * wmu_s[c0 + 1];
                mup[i][1] += h2c * wmu_s[c0] + h2d * wmu_s[c0 + 1];
            }
#pragma unroll
        for (int i = 0; i < 4; ++i)
#pragma unroll
            for (int hq = 0; hq < 2; ++hq) {
                float v = mup[i][hq];
                v += __shfl_xor_sync(0xffffffffu, v, 1);
                v += __shfl_xor_sync(0xffffffffu, v, 2);
                if ((lane & 3) == 0)
                    atomicAdd(&mu_s[wr * 64 + i * 16 + (lane >> 2) + hq * 8], v);
            }
    }
    __syncthreads();
    if (tid < 128) {
        out[BHL + (size_t)(b0 + tid) * 32 + l] = mu_s[tid] + __ldg(bmu + l);
        out[BHL + BLc + (size_t)(b0 + tid) * 32 + l] =
            fmaxf(__ldg(log_var + l), -3.0f);
    }
}

extern "C" void kernel_launch(void* const* d_in, const int* in_sizes, int n_in,
                              void* d_out, int out_size) {
    const float* hidden  = (const float*)d_in[0];
    const float* x       = (const float*)d_in[1];
    const float* mask    = (const float*)d_in[2];
    const float* Wir     = (const float*)d_in[3];
    const float* bir     = (const float*)d_in[4];
    const float* Wiz     = (const float*)d_in[5];
    const float* biz     = (const float*)d_in[6];
    const float* Win     = (const float*)d_in[7];
    const float* bin_    = (const float*)d_in[8];
    const float* Whr     = (const float*)d_in[9];
    const float* Whz     = (const float*)d_in[10];
    const float* Whn     = (const float*)d_in[11];
    const float* bhn     = (const float*)d_in[12];
    const float* W1      = (const float*)d_in[13];
    const float* b1      = (const float*)d_in[14];
    const float* W2      = (const float*)d_in[15];
    const float* b2      = (const float*)d_in[16];
    const float* Wmu     = (const float*)d_in[17];
    const float* bmu     = (const float*)d_in[18];
    const float* log_var = (const float*)d_in[19];
    float* out = (float*)d_out;

    cudaFuncSetAttribute(prnn_mma, cudaFuncAttributeMaxDynamicSharedMemorySize,
                         SMEM_BYTES);
    prnn_mma<<<1024, 256, SMEM_BYTES>>>(hidden, x, mask, Wir, bir, Wiz, biz,
                                        Win, bin_, Whr, Whz, Whn, bhn, W1, b1,
                                        W2, b2, Wmu, bmu, log_var, out);
}

// round 8
// speedup vs baseline: 2.0526x; 1.1761x over previous
#include <cuda_runtime.h>
#include <math.h>
#include <stdint.h>

// ParallelRNN via warp-level tf32 mma.sync. B=4096,H=256,L=32,I=64.
// R8: 512 thr (4 warps/SMSP), warp tile 32x64, 5-stage cp.async B ring
// (depth-4 prefetch), weights pre-rounded to tf32 by a prep kernel.

#define DEVI __device__ __forceinline__

static constexpr long long BHL = 4096LL * 256 * 32;
static constexpr long long BLc = 4096LL * 32;

static constexpr size_t HH_ONE = 32 * 65536;          // floats per HH weight
static constexpr size_t II_ONE = 32 * 16384;
static constexpr size_t HH_TOT = 5 * HH_ONE;          // 10485760
static constexpr size_t W_TOT  = HH_TOT + 3 * II_ONE; // 12058624

__device__ float g_wr[W_TOT];        // tf32-rounded weights (~48MB)
__device__ float g_scr[33554432];    // per-thread r/n scratch (128MB)

// smem map (bytes): A[0,131072) xm[131072,163840) Bring 5x8448[163840,206080)
//                   mu[206080,206592) wmu[206592,207616)
static constexpr unsigned SMEM_BYTES = 207616;

DEVI unsigned s2u(const void* p) {
    unsigned a;
    asm("{ .reg .u64 t; cvta.to.shared.u64 t, %1; cvt.u32.u64 %0, t; }"
        : "=r"(a) : "l"(p));
    return a;
}
DEVI float sigm(float v) { return __fdividef(1.f, 1.f + __expf(-v)); }
// 16B-unit swizzle: phys unit = (k4 & ~7) | ((k4 ^ row) & 7)
DEVI unsigned aswz(int row, int k4) {
    return (unsigned)(((k4 & ~7) | ((k4 ^ row) & 7)) * 16);
}

// ---------- prep: round all weights to tf32 (rna) once ----------
__global__ void __launch_bounds__(256)
wround(const float* __restrict__ Whr, const float* __restrict__ Whn,
       const float* __restrict__ Whz, const float* __restrict__ W1,
       const float* __restrict__ W2,  const float* __restrict__ Wir,
       const float* __restrict__ Win, const float* __restrict__ Wiz) {
    const float* hh[5] = {Whr, Whn, Whz, W1, W2};
    const float* ii[3] = {Wir, Win, Wiz};
    size_t g = (size_t)blockIdx.x * blockDim.x + threadIdx.x;
    size_t gs = (size_t)gridDim.x * blockDim.x;
    for (size_t i = g; i < W_TOT; i += gs) {
        float v;
        if (i < HH_TOT) v = hh[i / HH_ONE][i % HH_ONE];
        else {
            size_t j = i - HH_TOT;
            v = ii[j / II_ONE][j % II_ONE];
        }
        uint32_t o;
        asm("cvt.rna.tf32.f32 %0, %1;" : "=r"(o) : "f"(v));
        g_wr[i] = __uint_as_float(o);
    }
}

// ---- one GEMM segment: acc += Asm[128 x 8*nch] @ W[8*nch x 256] ----
template <int RS>   // A row stride in bytes (1024 for A, 256 for xm)
DEVI void gemm_seg(float (&acc)[2][8][4], unsigned aU, const float* __restrict__ W,
                   int nch, unsigned bU, int tid, int lane, int wr, int wc) {
    const int kk = tid >> 6, uu = tid & 63;       // 512 thr -> 16B each / chunk
#pragma unroll
    for (int p = 0; p < 4; ++p) {                 // prologue: chunks 0..3
        if (p < nch)
            asm volatile("cp.async.cg.shared.global [%0], [%1], 16;"
                :: "r"(bU + p * 8448u + kk * 1056 + uu * 16),
                   "l"((const char*)W + (size_t)p * 8192 + kk * 1024 + uu * 16));
        asm volatile("cp.async.commit_group;");
    }
    const int lm = lane >> 3, lr = lane & 7;
    for (int c = 0; c < nch; ++c) {
        asm volatile("cp.async.wait_group 3;");
        __syncthreads();
        if (c + 4 < nch)
            asm volatile("cp.async.cg.shared.global [%0], [%1], 16;"
                :: "r"(bU + (unsigned)((c + 4) % 5) * 8448u + kk * 1056 + uu * 16),
                   "l"((const char*)W + (size_t)(c + 4) * 8192 + kk * 1024 + uu * 16));
        asm volatile("cp.async.commit_group;");

        const unsigned bb = bU + (unsigned)(c % 5) * 8448u;
        uint32_t af[2][4];
#pragma unroll
        for (int i = 0; i < 2; ++i) {
            int row = wr * 32 + i * 16 + (lm & 1) * 8 + lr;
            int k4  = c * 2 + (lm >> 1);
            unsigned ad = aU + (unsigned)row * RS + aswz(row, k4);
            asm volatile("ldmatrix.sync.aligned.m8n8.x4.shared.b16 {%0,%1,%2,%3}, [%4];"
                : "=r"(af[i][0]), "=r"(af[i][1]), "=r"(af[i][2]), "=r"(af[i][3])
                : "r"(ad));
#pragma unroll
            for (int q = 0; q < 4; ++q)
                asm volatile("{.reg .f32 t; mov.b32 t, %0; cvt.rna.tf32.f32 %0, t;}"
                             : "+r"(af[i][q]));
        }
        uint32_t bf[8][2];
#pragma unroll
        for (int j = 0; j < 8; ++j) {      // weights pre-rounded: no cvt
            unsigned b0a = bb + (unsigned)(lane & 3) * 1056u
                         + (unsigned)(wc * 64 + j * 8 + (lane >> 2)) * 4u;
            asm volatile("ld.shared.b32 %0, [%1];" : "=r"(bf[j][0]) : "r"(b0a));
            asm volatile("ld.shared.b32 %0, [%1];" : "=r"(bf[j][1]) : "r"(b0a + 4224u));
        }
#pragma unroll
        for (int i = 0; i < 2; ++i)
#pragma unroll
            for (int j = 0; j < 8; ++j)
                asm volatile(
                    "mma.sync.aligned.m16n8k8.row.col.f32.tf32.tf32.f32 "
                    "{%0,%1,%2,%3}, {%4,%5,%6,%7}, {%8,%9}, {%0,%1,%2,%3};"
                    : "+f"(acc[i][j][0]), "+f"(acc[i][j][1]),
                      "+f"(acc[i][j][2]), "+f"(acc[i][j][3])
                    : "r"(af[i][0]), "r"(af[i][1]), "r"(af[i][2]), "r"(af[i][3]),
                      "r"(bf[j][0]), "r"(bf[j][1]));
    }
    __syncthreads();   // A reads done before epilogue writes / next segment
}

__global__ void __launch_bounds__(512, 1)
prnn_mma(const float* __restrict__ hidden, const float* __restrict__ x,
         const float* __restrict__ mask,
         const float* __restrict__ bir, const float* __restrict__ biz,
         const float* __restrict__ bin_, const float* __restrict__ bhn,
         const float* __restrict__ b1,  const float* __restrict__ b2,
         const float* __restrict__ Wmu, const float* __restrict__ bmu,
         const float* __restrict__ log_var, float* __restrict__ out) {
    extern __shared__ __align__(16) char smem[];
    const unsigned sU = s2u(smem);
    const unsigned aU = sU, xU = sU + 131072u, bU = sU + 163840u;
    float* mu_s  = (float*)(smem + 206080);
    float* wmu_s = (float*)(smem + 206592);
    const int tid = threadIdx.x, lane = tid & 31, w = tid >> 5;
    const int wr = w >> 2, wc = w & 3;           // warp grid 4 x 4
    const int l = blockIdx.x & 31, b0 = (blockIdx.x >> 5) * 128;

    if (tid < 128) mu_s[tid] = 0.f;
    if (tid < 256) wmu_s[tid] = __ldg(Wmu + l * 256 + tid);

    {   // A <- h (scattered gmem, swizzled smem); thread = (col, row-half)
        const int colA = tid & 255, rh = tid >> 8;
        const float* hp = hidden + (size_t)(b0 + rh * 64) * 8192
                        + (size_t)colA * 32 + l;
#pragma unroll 4
        for (int r = 0; r < 64; ++r) {
            float v = hp[(size_t)r * 8192];
            int row = rh * 64 + r;
            unsigned ad = aU + (unsigned)row * 1024u + aswz(row, colA >> 2)
                        + (colA & 3) * 4u;
            asm volatile("st.shared.f32 [%0], %1;" :: "r"(ad), "f"(v));
        }
    }
    {   // xm <- x * mask
#pragma unroll
        for (int q = 0; q < 16; ++q) {
            int idx = tid + q * 512, r = idx >> 6, k = idx & 63;
            float v = __ldg(x + (size_t)(b0 + r) * 64 + k) * __ldg(mask + k * 32 + l);
            unsigned ad = xU + (unsigned)r * 256u + aswz(r, k >> 2) + (k & 3) * 4u;
            asm volatile("st.shared.f32 [%0], %1;" :: "r"(ad), "f"(v));
        }
    }

    float acc[2][8][4];
    float* scr = g_scr + (size_t)blockIdx.x * 32768 + (size_t)w * 2048;
    const float* WH = g_wr;
    const float* WI = g_wr + HH_TOT;

#define ZACC()                                                                \
    _Pragma("unroll") for (int i = 0; i < 2; ++i)                             \
    _Pragma("unroll") for (int j = 0; j < 8; ++j)                             \
    _Pragma("unroll") for (int q = 0; q < 4; ++q) acc[i][j][q] = 0.f;
#define C0J (wc * 64 + j * 8 + 2 * (lane & 3))
#define R0I (wr * 32 + i * 16 + (lane >> 2))
#define SCRP(i, j) (scr + ((size_t)((i) * 8 + (j)) * 32 + lane) * 4)

    // seg1: r = sigmoid(h@Whr + xm@Wir + bir) -> scratch
    ZACC();
    gemm_seg<1024>(acc, aU, WH + (size_t)(0 * 32 + l) * 65536, 32, bU, tid, lane, wr, wc);
    gemm_seg<256>(acc, xU, WI + (size_t)(0 * 32 + l) * 16384, 8, bU, tid, lane, wr, wc);
    {
        const float* bb = bir + l * 256;
#pragma unroll
        for (int i = 0; i < 2; ++i)
#pragma unroll
            for (int j = 0; j < 8; ++j) {
                int c0 = C0J;
                float4 v;
                v.x = sigm(acc[i][j][0] + __ldg(bb + c0));
                v.y = sigm(acc[i][j][1] + __ldg(bb + c0 + 1));
                v.z = sigm(acc[i][j][2] + __ldg(bb + c0));
                v.w = sigm(acc[i][j][3] + __ldg(bb + c0 + 1));
                *reinterpret_cast<float4*>(SCRP(i, j)) = v;
            }
    }
    // seg2: acc = h@Whn; t = r*(acc+bhn); acc += xm@Win; n = tanh(acc+bin) -> scratch
    ZACC();
    gemm_seg<1024>(acc, aU, WH + (size_t)(1 * 32 + l) * 65536, 32, bU, tid, lane, wr, wc);
    {
        const float* bb = bhn + l * 256;
#pragma unroll
        for (int i = 0; i < 2; ++i)
#pragma unroll
            for (int j = 0; j < 8; ++j) {
                int c0 = C0J;
                float4 rv = *reinterpret_cast<const float4*>(SCRP(i, j));
                acc[i][j][0] = rv.x * (acc[i][j][0] + __ldg(bb + c0));
                acc[i][j][1] = rv.y * (acc[i][j][1] + __ldg(bb + c0 + 1));
                acc[i][j][2] = rv.z * (acc[i][j][2] + __ldg(bb + c0));
                acc[i][j][3] = rv.w * (acc[i][j][3] + __ldg(bb + c0 + 1));
            }
    }
    gemm_seg<256>(acc, xU, WI + (size_t)(1 * 32 + l) * 16384, 8, bU, tid, lane, wr, wc);
    {
        const float* bb = bin_ + l * 256;
#pragma unroll
        for (int i = 0; i < 2; ++i)
#pragma unroll
            for (int j = 0; j < 8; ++j) {
                int c0 = C0J;
                float4 v;
                v.x = tanhf(acc[i][j][0] + __ldg(bb + c0));
                v.y = tanhf(acc[i][j][1] + __ldg(bb + c0 + 1));
                v.z = tanhf(acc[i][j][2] + __ldg(bb + c0));
                v.w = tanhf(acc[i][j][3] + __ldg(bb + c0 + 1));
                *reinterpret_cast<float4*>(SCRP(i, j)) = v;
            }
    }
    // seg3: z = sigmoid(h@Whz + xm@Wiz + biz); hnew = n + z*(h-n) -> A in place
    ZACC();
    gemm_seg<1024>(acc, aU, WH + (size_t)(2 * 32 + l) * 65536, 32, bU, tid, lane, wr, wc);
    gemm_seg<256>(acc, xU, WI + (size_t)(2 * 32 + l) * 16384, 8, bU, tid, lane, wr, wc);
    {
        const float* bb = biz + l * 256;
#pragma unroll
        for (int i = 0; i < 2; ++i)
#pragma unroll
            for (int j = 0; j < 8; ++j) {
                int c0 = C0J, r0 = R0I, r1 = r0 + 8;
                float4 nv = *reinterpret_cast<const float4*>(SCRP(i, j));
                float zz[4];
                zz[0] = sigm(acc[i][j][0] + __ldg(bb + c0));
                zz[1] = sigm(acc[i][j][1] + __ldg(bb + c0 + 1));
                zz[2] = sigm(acc[i][j][2] + __ldg(bb + c0));
                zz[3] = sigm(acc[i][j][3] + __ldg(bb + c0 + 1));
                const int rr[4] = {r0, r0, r1, r1};
                const int cc[4] = {c0, c0 + 1, c0, c0 + 1};
                const float nn[4] = {nv.x, nv.y, nv.z, nv.w};
#pragma unroll
                for (int q = 0; q < 4; ++q) {
                    unsigned ad = aU + (unsigned)rr[q] * 1024u
                                + aswz(rr[q], cc[q] >> 2) + (cc[q] & 3) * 4u;
                    float h;
                    asm volatile("ld.shared.f32 %0, [%1];" : "=f"(h) : "r"(ad));
                    float hv = nn[q] + zz[q] * (h - nn[q]);
                    asm volatile("st.shared.f32 [%0], %1;" :: "r"(ad), "f"(hv));
                }
            }
    }
    __syncthreads();
    // seg4: h1 = relu(hnew@W1 + b1) -> A
    ZACC();
    gemm_seg<1024>(acc, aU, WH + (size_t)(3 * 32 + l) * 65536, 32, bU, tid, lane, wr, wc);
    {
        const float* bb = b1 + l * 256;
#pragma unroll
        for (int i = 0; i < 2; ++i)
#pragma unroll
            for (int j = 0; j < 8; ++j) {
                int c0 = C0J, r0 = R0I, r1 = r0 + 8;
                const int rr[4] = {r0, r0, r1, r1};
                const int cc[4] = {c0, c0 + 1, c0, c0 + 1};
#pragma unroll
                for (int q = 0; q < 4; ++q) {
                    float hv = fmaxf(acc[i][j][q] + __ldg(bb + cc[q]), 0.f);
                    unsigned ad = aU + (unsigned)rr[q] * 1024u
                                + aswz(rr[q], cc[q] >> 2) + (cc[q] & 3) * 4u;
                    asm volatile("st.shared.f32 [%0], %1;" :: "r"(ad), "f"(hv));
                }
            }
    }
    __syncthreads();
    // seg5: h2 = relu(h1@W2 + b2) -> out + mu
    ZACC();
    gemm_seg<1024>(acc, aU, WH + (size_t)(4 * 32 + l) * 65536, 32, bU, tid, lane, wr, wc);
    {
        const float* bb = b2 + l * 256;
        float mup[2][2];
#pragma unroll
        for (int i = 0; i < 2; ++i) { mup[i][0] = 0.f; mup[i][1] = 0.f; }
#pragma unroll
        for (int i = 0; i < 2; ++i)
#pragma unroll
            for (int j = 0; j < 8; ++j) {
                int c0 = C0J, r0 = R0I, r1 = r0 + 8;
                float h2a = fmaxf(acc[i][j][0] + __ldg(bb + c0), 0.f);
                float h2b = fmaxf(acc[i][j][1] + __ldg(bb + c0 + 1), 0.f);
                float h2c = fmaxf(acc[i][j][2] + __ldg(bb + c0), 0.f);
                float h2d = fmaxf(acc[i][j][3] + __ldg(bb + c0 + 1), 0.f);
                size_t ob  = (size_t)(b0 + r0) * 8192 + l;
                size_t ob1 = (size_t)(b0 + r1) * 8192 + l;
                out[ob + (size_t)c0 * 32]        = h2a;
                out[ob + (size_t)(c0 + 1) * 32]  = h2b;
                out[ob1 + (size_t)c0 * 32]       = h2c;
                out[ob1 + (size_t)(c0 + 1) * 32] = h2d;
                mup[i][0] += h2a * wmu_s[c0] + h2b * wmu_s[c0 + 1];
                mup[i][1] += h2c * wmu_s[c0] + h2d * wmu_s[c0 + 1];
            }
#pragma unroll
        for (int i = 0; i < 2; ++i)
#pragma unroll
            for (int hq = 0; hq < 2; ++hq) {
                float v = mup[i][hq];
                v += __shfl_xor_sync(0xffffffffu, v, 1);
                v += __shfl_xor_sync(0xffffffffu, v, 2);
                if ((lane & 3) == 0)
                    atomicAdd(&mu_s[wr * 32 + i * 16 + (lane >> 2) + hq * 8], v);
            }
    }
    __syncthreads();
    if (tid < 128) {
        out[BHL + (size_t)(b0 + tid) * 32 + l] = mu_s[tid] + __ldg(bmu + l);
        out[BHL + BLc + (size_t)(b0 + tid) * 32 + l] =
            fmaxf(__ldg(log_var + l), -3.0f);
    }
}

extern "C" void kernel_launch(void* const* d_in, const int* in_sizes, int n_in,
                              void* d_out, int out_size) {
    const float* hidden  = (const float*)d_in[0];
    const float* x       = (const float*)d_in[1];
    const float* mask    = (const float*)d_in[2];
    const float* Wir     = (const float*)d_in[3];
    const float* bir     = (const float*)d_in[4];
    const float* Wiz     = (const float*)d_in[5];
    const float* biz     = (const float*)d_in[6];
    const float* Win     = (const float*)d_in[7];
    const float* bin_    = (const float*)d_in[8];
    const float* Whr     = (const float*)d_in[9];
    const float* Whz     = (const float*)d_in[10];
    const float* Whn     = (const float*)d_in[11];
    const float* bhn     = (const float*)d_in[12];
    const float* W1      = (const float*)d_in[13];
    const float* b1      = (const float*)d_in[14];
    const float* W2      = (const float*)d_in[15];
    const float* b2      = (const float*)d_in[16];
    const float* Wmu     = (const float*)d_in[17];
    const float* bmu     = (const float*)d_in[18];
    const float* log_var = (const float*)d_in[19];
    float* out = (float*)d_out;

    cudaFuncSetAttribute(prnn_mma, cudaFuncAttributeMaxDynamicSharedMemorySize,
                         SMEM_BYTES);
    wround<<<2048, 256>>>(Whr, Whn, Whz, W1, W2, Wir, Win, Wiz);
    prnn_mma<<<1024, 512, SMEM_BYTES>>>(hidden, x, mask, bir, biz, bin_, bhn,
                                        b1, b2, Wmu, bmu, log_var, out);
}

// round 9
// speedup vs baseline: 2.2779x; 1.1098x over previous
#include <cuda_runtime.h>
#include <math.h>
#include <stdint.h>

// ParallelRNN via warp-level tf32 mma.sync. B=4096,H=256,L=32,I=64.
// R9: k16 chunks (half the barriers), fragment-ordered weight images
// (B-frags = 8x conflict-free LDS.128), A pre-rounded to tf32 in smem
// (no mainloop cvt). 512 thr, warp tile 32x64, ring 3x16KB.

#define DEVI __device__ __forceinline__

static constexpr long long BHL = 4096LL * 256 * 32;
static constexpr long long BLc = 4096LL * 32;

static constexpr size_t HH_ONE = 32 * 65536;          // floats per HH weight (all l)
static constexpr size_t II_ONE = 32 * 16384;
static constexpr size_t HH_TOT = 5 * HH_ONE;
static constexpr size_t W_TOT  = HH_TOT + 3 * II_ONE;

__device__ float g_wr[W_TOT];        // fragment-ordered tf32 weights (~48MB)
__device__ float g_scr[33554432];    // per-thread r/n scratch

// smem map (bytes): A[0,131072) xm[131072,163840) Bring 3x16384[163840,212992)
//                   mu[212992,213504) wmu[213504,214528)
static constexpr unsigned SMEM_BYTES = 214528;

DEVI unsigned s2u(const void* p) {
    unsigned a;
    asm("{ .reg .u64 t; cvta.to.shared.u64 t, %1; cvt.u32.u64 %0, t; }"
        : "=r"(a) : "l"(p));
    return a;
}
DEVI float sigm(float v) { return __fdividef(1.f, 1.f + __expf(-v)); }
DEVI float tf32r(float v) {
    uint32_t o;
    asm("cvt.rna.tf32.f32 %0, %1;" : "=r"(o) : "f"(v));
    return __uint_as_float(o);
}
// 16B-unit swizzle for A: phys unit = (k4 & ~7) | ((k4 ^ row) & 7)
DEVI unsigned aswz(int row, int k4) {
    return (unsigned)(((k4 & ~7) | ((k4 ^ row) & 7)) * 16);
}

// ---------- prep: build fragment-ordered tf32 weight images ----------
// chunk16 layout (4096 floats): float4 index fq*128 + wc*32 + lane,
// fq = s*4 + j4; float4 = (j=2j4:b0, j=2j4:b1, j=2j4+1:b0, j=2j4+1:b1)
// where value(j,b) = W[k = 16c + 8s + (lane&3) + 4b][n = 64wc + 8j + (lane>>2)]
__global__ void __launch_bounds__(256)
wprep(const float* __restrict__ Whr, const float* __restrict__ Whn,
      const float* __restrict__ Whz, const float* __restrict__ W1,
      const float* __restrict__ W2,  const float* __restrict__ Wir,
      const float* __restrict__ Win, const float* __restrict__ Wiz) {
    const int bid = blockIdx.x, tid = threadIdx.x;
    const float* src;
    float* dst;
    int c;
    if (bid < 2560) {                 // 5 HH x 32 l x 16 chunks
        int w = bid >> 9, rem = bid & 511, l = rem >> 4;
        c = rem & 15;
        const float* hs[5] = {Whr, Whn, Whz, W1, W2};
        src = hs[w] + (size_t)l * 65536;
        dst = g_wr + (size_t)(w * 32 + l) * 65536 + (size_t)c * 4096;
    } else {                          // 3 II x 32 l x 4 chunks
        int e = bid - 2560;
        int w = e >> 7, rem = e & 127, l = rem >> 2;
        c = rem & 3;
        const float* is[3] = {Wir, Win, Wiz};
        src = is[w] + (size_t)l * 16384;
        dst = g_wr + HH_TOT + (size_t)(w * 32 + l) * 16384 + (size_t)c * 4096;
    }
    const int s = tid >> 7, wc = (tid >> 5) & 3, lane = tid & 31;
#pragma unroll
    for (int j4 = 0; j4 < 4; ++j4) {
        float4 v;
        int k0 = c * 16 + s * 8 + (lane & 3);
        int n0 = wc * 64 + (2 * j4) * 8 + (lane >> 2);
        int n1 = n0 + 8;
        v.x = tf32r(src[(size_t)k0 * 256 + n0]);
        v.y = tf32r(src[(size_t)(k0 + 4) * 256 + n0]);
        v.z = tf32r(src[(size_t)k0 * 256 + n1]);
        v.w = tf32r(src[(size_t)(k0 + 4) * 256 + n1]);
        reinterpret_cast<float4*>(dst)[(s * 4 + j4) * 128 + wc * 32 + lane] = v;
    }
}

// ---- one GEMM segment: acc += Asm[128 x 16*nch] @ W[16*nch x 256] ----
template <int RS>   // A row stride in bytes (1024 for A, 256 for xm)
DEVI void gemm_seg(float (&acc)[2][8][4], unsigned aU, const float* __restrict__ W,
                   int nch, unsigned bU, int tid, int lane, int wr, int wc) {
#pragma unroll
    for (int p = 0; p < 2; ++p) {                 // prologue: chunks 0,1
        const char* src = (const char*)W + (size_t)p * 16384 + tid * 32;
        unsigned dst = bU + (unsigned)p * 16384u + (unsigned)tid * 32u;
        asm volatile("cp.async.cg.shared.global [%0], [%1], 16;" :: "r"(dst), "l"(src));
        asm volatile("cp.async.cg.shared.global [%0], [%1], 16;"
                     :: "r"(dst + 16u), "l"(src + 16));
        asm volatile("cp.async.commit_group;");
    }
    const int lm = lane >> 3, lr = lane & 7;
    const unsigned bfb = (unsigned)(wc * 32 + lane) * 16u;
    for (int c = 0; c < nch; ++c) {
        asm volatile("cp.async.wait_group 1;");
        __syncthreads();
        if (c + 2 < nch) {
            const char* src = (const char*)W + (size_t)(c + 2) * 16384 + tid * 32;
            unsigned dst = bU + (unsigned)((c + 2) % 3) * 16384u + (unsigned)tid * 32u;
            asm volatile("cp.async.cg.shared.global [%0], [%1], 16;" :: "r"(dst), "l"(src));
            asm volatile("cp.async.cg.shared.global [%0], [%1], 16;"
                         :: "r"(dst + 16u), "l"(src + 16));
        }
        asm volatile("cp.async.commit_group;");

        const unsigned bb = bU + (unsigned)(c % 3) * 16384u;
#pragma unroll
        for (int s = 0; s < 2; ++s) {
            uint32_t bf[8][2];
#pragma unroll
            for (int j4 = 0; j4 < 4; ++j4) {
                uint32_t v0, v1, v2, v3;
                asm volatile("ld.shared.v4.b32 {%0,%1,%2,%3}, [%4];"
                    : "=r"(v0), "=r"(v1), "=r"(v2), "=r"(v3)
                    : "r"(bb + (unsigned)(s * 4 + j4) * 2048u + bfb));
                bf[2 * j4][0] = v0; bf[2 * j4][1] = v1;
                bf[2 * j4 + 1][0] = v2; bf[2 * j4 + 1][1] = v3;
            }
            uint32_t af[2][4];
#pragma unroll
            for (int i = 0; i < 2; ++i) {
                int row = wr * 32 + i * 16 + (lm & 1) * 8 + lr;
                int k4  = c * 4 + s * 2 + (lm >> 1);
                unsigned ad = aU + (unsigned)row * RS + aswz(row, k4);
                asm volatile("ldmatrix.sync.aligned.m8n8.x4.shared.b16 {%0,%1,%2,%3}, [%4];"
                    : "=r"(af[i][0]), "=r"(af[i][1]), "=r"(af[i][2]), "=r"(af[i][3])
                    : "r"(ad));
            }
#pragma unroll
            for (int i = 0; i < 2; ++i)
#pragma unroll
                for (int j = 0; j < 8; ++j)
                    asm volatile(
                        "mma.sync.aligned.m16n8k8.row.col.f32.tf32.tf32.f32 "
                        "{%0,%1,%2,%3}, {%4,%5,%6,%7}, {%8,%9}, {%0,%1,%2,%3};"
                        : "+f"(acc[i][j][0]), "+f"(acc[i][j][1]),
                          "+f"(acc[i][j][2]), "+f"(acc[i][j][3])
                        : "r"(af[i][0]), "r"(af[i][1]), "r"(af[i][2]), "r"(af[i][3]),
                          "r"(bf[j][0]), "r"(bf[j][1]));
        }
    }
    __syncthreads();   // A reads done before epilogue writes / next segment
}

__global__ void __launch_bounds__(512, 1)
prnn_mma(const float* __restrict__ hidden, const float* __restrict__ x,
         const float* __restrict__ mask,
         const float* __restrict__ bir, const float* __restrict__ biz,
         const float* __restrict__ bin_, const float* __restrict__ bhn,
         const float* __restrict__ b1,  const float* __restrict__ b2,
         const float* __restrict__ Wmu, const float* __restrict__ bmu,
         const float* __restrict__ log_var, float* __restrict__ out) {
    extern __shared__ __align__(16) char smem[];
    const unsigned sU = s2u(smem);
    const unsigned aU = sU, xU = sU + 131072u, bU = sU + 163840u;
    float* mu_s  = (float*)(smem + 212992);
    float* wmu_s = (float*)(smem + 213504);
    const int tid = threadIdx.x, lane = tid & 31, w = tid >> 5;
    const int wr = w >> 2, wc = w & 3;           // warp grid 4 x 4
    const int l = blockIdx.x & 31, b0 = (blockIdx.x >> 5) * 128;

    if (tid < 128) mu_s[tid] = 0.f;
    if (tid < 256) wmu_s[tid] = __ldg(Wmu + l * 256 + tid);

    {   // A <- tf32(h) (scattered gmem, swizzled smem); thread = (col, row-half)
        const int colA = tid & 255, rh = tid >> 8;
        const float* hp = hidden + (size_t)(b0 + rh * 64) * 8192
                        + (size_t)colA * 32 + l;
#pragma unroll 4
        for (int r = 0; r < 64; ++r) {
            float v = tf32r(hp[(size_t)r * 8192]);
            int row = rh * 64 + r;
            unsigned ad = aU + (unsigned)row * 1024u + aswz(row, colA >> 2)
                        + (colA & 3) * 4u;
            asm volatile("st.shared.f32 [%0], %1;" :: "r"(ad), "f"(v));
        }
    }
    {   // xm <- tf32(x * mask)
#pragma unroll
        for (int q = 0; q < 16; ++q) {
            int idx = tid + q * 512, r = idx >> 6, k = idx & 63;
            float v = tf32r(__ldg(x + (size_t)(b0 + r) * 64 + k)
                            * __ldg(mask + k * 32 + l));
            unsigned ad = xU + (unsigned)r * 256u + aswz(r, k >> 2) + (k & 3) * 4u;
            asm volatile("st.shared.f32 [%0], %1;" :: "r"(ad), "f"(v));
        }
    }

    float acc[2][8][4];
    float* scr = g_scr + (size_t)blockIdx.x * 32768 + (size_t)w * 2048;
    const float* WH = g_wr;
    const float* WI = g_wr + HH_TOT;

#define ZACC()                                                                \
    _Pragma("unroll") for (int i = 0; i < 2; ++i)                             \
    _Pragma("unroll") for (int j = 0; j < 8; ++j)                             \
    _Pragma("unroll") for (int q = 0; q < 4; ++q) acc[i][j][q] = 0.f;
#define C0J (wc * 64 + j * 8 + 2 * (lane & 3))
#define R0I (wr * 32 + i * 16 + (lane >> 2))
#define SCRP(i, j) (scr + ((size_t)((i) * 8 + (j)) * 32 + lane) * 4)

    // seg1: r = sigmoid(h@Whr + xm@Wir + bir) -> scratch
    ZACC();
    gemm_seg<1024>(acc, aU, WH + (size_t)(0 * 32 + l) * 65536, 16, bU, tid, lane, wr, wc);
    gemm_seg<256>(acc, xU, WI + (size_t)(0 * 32 + l) * 16384, 4, bU, tid, lane, wr, wc);
    {
        const float* bb = bir + l * 256;
#pragma unroll
        for (int i = 0; i < 2; ++i)
#pragma unroll
            for (int j = 0; j < 8; ++j) {
                int c0 = C0J;
                float4 v;
                v.x = sigm(acc[i][j][0] + __ldg(bb + c0));
                v.y = sigm(acc[i][j][1] + __ldg(bb + c0 + 1));
                v.z = sigm(acc[i][j][2] + __ldg(bb + c0));
                v.w = sigm(acc[i][j][3] + __ldg(bb + c0 + 1));
                *reinterpret_cast<float4*>(SCRP(i, j)) = v;
            }
    }
    // seg2: acc = h@Whn; t = r*(acc+bhn); acc += xm@Win; n = tanh(acc+bin) -> scratch
    ZACC();
    gemm_seg<1024>(acc, aU, WH + (size_t)(1 * 32 + l) * 65536, 16, bU, tid, lane, wr, wc);
    {
        const float* bb = bhn + l * 256;
#pragma unroll
        for (int i = 0; i < 2; ++i)
#pragma unroll
            for (int j = 0; j < 8; ++j) {
                int c0 = C0J;
                float4 rv = *reinterpret_cast<const float4*>(SCRP(i, j));
                acc[i][j][0] = rv.x * (acc[i][j][0] + __ldg(bb + c0));
                acc[i][j][1] = rv.y * (acc[i][j][1] + __ldg(bb + c0 + 1));
                acc[i][j][2] = rv.z * (acc[i][j][2] + __ldg(bb + c0));
                acc[i][j][3] = rv.w * (acc[i][j][3] + __ldg(bb + c0 + 1));
            }
    }
    gemm_seg<256>(acc, xU, WI + (size_t)(1 * 32 + l) * 16384, 4, bU, tid, lane, wr, wc);
    {
        const float* bb = bin_ + l * 256;
#pragma unroll
        for (int i = 0; i < 2; ++i)
#pragma unroll
            for (int j = 0; j < 8; ++j) {
                int c0 = C0J;
                float4 v;
                v.x = tanhf(acc[i][j][0] + __ldg(bb + c0));
                v.y = tanhf(acc[i][j][1] + __ldg(bb + c0 + 1));
                v.z = tanhf(acc[i][j][2] + __ldg(bb + c0));
                v.w = tanhf(acc[i][j][3] + __ldg(bb + c0 + 1));
                *reinterpret_cast<float4*>(SCRP(i, j)) = v;
            }
    }
    // seg3: z = sigmoid(h@Whz + xm@Wiz + biz); hnew = n + z*(h-n) -> A (tf32)
    ZACC();
    gemm_seg<1024>(acc, aU, WH + (size_t)(2 * 32 + l) * 65536, 16, bU, tid, lane, wr, wc);
    gemm_seg<256>(acc, xU, WI + (size_t)(2 * 32 + l) * 16384, 4, bU, tid, lane, wr, wc);
    {
        const float* bb = biz + l * 256;
#pragma unroll
        for (int i = 0; i < 2; ++i)
#pragma unroll
            for (int j = 0; j < 8; ++j) {
                int c0 = C0J, r0 = R0I, r1 = r0 + 8;
                float4 nv = *reinterpret_cast<const float4*>(SCRP(i, j));
                float zz[4];
                zz[0] = sigm(acc[i][j][0] + __ldg(bb + c0));
                zz[1] = sigm(acc[i][j][1] + __ldg(bb + c0 + 1));
                zz[2] = sigm(acc[i][j][2] + __ldg(bb + c0));
                zz[3] = sigm(acc[i][j][3] + __ldg(bb + c0 + 1));
                const int rr[4] = {r0, r0, r1, r1};
                const int cc[4] = {c0, c0 + 1, c0, c0 + 1};
                const float nn[4] = {nv.x, nv.y, nv.z, nv.w};
#pragma unroll
                for (int q = 0; q < 4; ++q) {
                    unsigned ad = aU + (unsigned)rr[q] * 1024u
                                + aswz(rr[q], cc[q] >> 2) + (cc[q] & 3) * 4u;
                    float h;
                    asm volatile("ld.shared.f32 %0, [%1];" : "=f"(h) : "r"(ad));
                    float hv = tf32r(nn[q] + zz[q] * (h - nn[q]));
                    asm volatile("st.shared.f32 [%0], %1;" :: "r"(ad), "f"(hv));
                }
            }
    }
    __syncthreads();
    // seg4: h1 = relu(hnew@W1 + b1) -> A (tf32)
    ZACC();
    gemm_seg<1024>(acc, aU, WH + (size_t)(3 * 32 + l) * 65536, 16, bU, tid, lane, wr, wc);
    {
        const float* bb = b1 + l * 256;
#pragma unroll
        for (int i = 0; i < 2; ++i)
#pragma unroll
            for (int j = 0; j < 8; ++j) {
                int c0 = C0J, r0 = R0I, r1 = r0 + 8;
                const int rr[4] = {r0, r0, r1, r1};
                const int cc[4] = {c0, c0 + 1, c0, c0 + 1};
#pragma unroll
                for (int q = 0; q < 4; ++q) {
                    float hv = tf32r(fmaxf(acc[i][j][q] + __ldg(bb + cc[q]), 0.f));
                    unsigned ad = aU + (unsigned)rr[q] * 1024u
                                + aswz(rr[q], cc[q] >> 2) + (cc[q] & 3) * 4u;
                    asm volatile("st.shared.f32 [%0], %1;" :: "r"(ad), "f"(hv));
                }
            }
    }
    __syncthreads();
    // seg5: h2 = relu(h1@W2 + b2) -> out + mu
    ZACC();
    gemm_seg<1024>(acc, aU, WH + (size_t)(4 * 32 + l) * 65536, 16, bU, tid, lane, wr, wc);
    {
        const float* bb = b2 + l * 256;
        float mup[2][2];
#pragma unroll
        for (int i = 0; i < 2; ++i) { mup[i][0] = 0.f; mup[i][1] = 0.f; }
#pragma unroll
        for (int i = 0; i < 2; ++i)
#pragma unroll
            for (int j = 0; j < 8; ++j) {
                int c0 = C0J, r0 = R0I, r1 = r0 + 8;
                float h2a = fmaxf(acc[i][j][0] + __ldg(bb + c0), 0.f);
                float h2b = fmaxf(acc[i][j][1] + __ldg(bb + c0 + 1), 0.f);
                float h2c = fmaxf(acc[i][j][2] + __ldg(bb + c0), 0.f);
                float h2d = fmaxf(acc[i][j][3] + __ldg(bb + c0 + 1), 0.f);
                size_t ob  = (size_t)(b0 + r0) * 8192 + l;
                size_t ob1 = (size_t)(b0 + r1) * 8192 + l;
                out[ob + (size_t)c0 * 32]        = h2a;
                out[ob + (size_t)(c0 + 1) * 32]  = h2b;
                out[ob1 + (size_t)c0 * 32]       = h2c;
                out[ob1 + (size_t)(c0 + 1) * 32] = h2d;
                mup[i][0] += h2a * wmu_s[c0] + h2b * wmu_s[c0 + 1];
                mup[i][1] += h2c * wmu_s[c0] + h2d * wmu_s[c0 + 1];
            }
#pragma unroll
        for (int i = 0; i < 2; ++i)
#pragma unroll
            for (int hq = 0; hq < 2; ++hq) {
                float v = mup[i][hq];
                v += __shfl_xor_sync(0xffffffffu, v, 1);
                v += __shfl_xor_sync(0xffffffffu, v, 2);
                if ((lane & 3) == 0)
                    atomicAdd(&mu_s[wr * 32 + i * 16 + (lane >> 2) + hq * 8], v);
            }
    }
    __syncthreads();
    if (tid < 128) {
        out[BHL + (size_t)(b0 + tid) * 32 + l] = mu_s[tid] + __ldg(bmu + l);
        out[BHL + BLc + (size_t)(b0 + tid) * 32 + l] =
            fmaxf(__ldg(log_var + l), -3.0f);
    }
}

extern "C" void kernel_launch(void* const* d_in, const int* in_sizes, int n_in,
                              void* d_out, int out_size) {
    const float* hidden  = (const float*)d_in[0];
    const float* x       = (const float*)d_in[1];
    const float* mask    = (const float*)d_in[2];
    const float* Wir     = (const float*)d_in[3];
    const float* bir     = (const float*)d_in[4];
    const float* Wiz     = (const float*)d_in[5];
    const float* biz     = (const float*)d_in[6];
    const float* Win     = (const float*)d_in[7];
    const float* bin_    = (const float*)d_in[8];
    const float* Whr     = (const float*)d_in[9];
    const float* Whz     = (const float*)d_in[10];
    const float* Whn     = (const float*)d_in[11];
    const float* bhn     = (const float*)d_in[12];
    const float* W1      = (const float*)d_in[13];
    const float* b1      = (const float*)d_in[14];
    const float* W2      = (const float*)d_in[15];
    const float* b2      = (const float*)d_in[16];
    const float* Wmu     = (const float*)d_in[17];
    const float* bmu     = (const float*)d_in[18];
    const float* log_var = (const float*)d_in[19];
    float* out = (float*)d_out;

    cudaFuncSetAttribute(prnn_mma, cudaFuncAttributeMaxDynamicSharedMemorySize,
                         SMEM_BYTES);
    wprep<<<2944, 256>>>(Whr, Whn, Whz, W1, W2, Wir, Win, Wiz);
    prnn_mma<<<1024, 512, SMEM_BYTES>>>(hidden, x, mask, bir, biz, bin_, bhn,
                                        b1, b2, Wmu, bmu, log_var, out);
}